// round 16
// baseline (speedup 1.0000x reference)
#include <cuda_runtime.h>
#include <cuda_fp16.h>
#include <cstdint>
#include <cstddef>

// Problem dims (fixed by the dataset)
#define BB 8
#define TC 2048
#define TQ 1024
#define DD 1024

// ---------------- scratch (allocation-free: __device__ globals) ----------------
__device__ __align__(256) __half g_attn[(size_t)BB * TC * TQ];  // fp16 softmax probs, 32 MiB
__device__ __align__(256) __half g_qt[(size_t)BB * DD * TQ];    // fp16 qencode^T [b][d][q], 16 MiB

// ---------------- helpers ----------------
__device__ __forceinline__ uint32_t smem_u32(const void* p) {
    uint32_t a;
    asm("{ .reg .u64 t; cvta.to.shared.u64 t, %1; cvt.u32.u64 %0, t; }" : "=r"(a) : "l"(p));
    return a;
}
// 1D bulk async copy global->shared, mbarrier complete_tx (sm_90 base ISA)
__device__ __forceinline__ void bulk_g2s(uint32_t dst, const void* src, uint32_t bytes,
                                         uint32_t mbar) {
    asm volatile(
        "cp.async.bulk.shared::cluster.global.mbarrier::complete_tx::bytes [%0], [%1], %2, [%3];"
        :: "r"(dst), "l"(src), "r"(bytes), "r"(mbar) : "memory");
}
#define MBARRIER_INIT(addr, cnt) \
    asm volatile("mbarrier.init.shared.b64 [%0], %1;" :: "r"((uint32_t)(addr)), "r"((uint32_t)(cnt)) : "memory")
#define MBARRIER_EXPECT_TX(addr, bytes) \
    asm volatile("mbarrier.arrive.expect_tx.shared.b64 _, [%0], %1;" \
        :: "r"((uint32_t)(addr)), "r"((uint32_t)(bytes)) : "memory")
#define MBARRIER_WAIT_PARITY(mbar_smem_addr, phase_parity) do { \
    uint32_t _mbar = (uint32_t)(mbar_smem_addr); \
    uint32_t _parity = (uint32_t)(phase_parity); \
    uint32_t _done; \
    asm volatile( \
        "{\n\t.reg .pred p;\n\t" \
        "mbarrier.try_wait.parity.acquire.cta.shared::cta.b64 p, [%1], %2;\n\t" \
        "selp.b32 %0, 1, 0, p;\n\t}" \
        : "=r"(_done) : "r"(_mbar), "r"(_parity) : "memory"); \
    if (!_done) { \
        asm volatile( \
            "{\n\t.reg .pred P1;\n\t" \
            "WAIT_LOOP_%=:\n\t" \
            "mbarrier.try_wait.parity.acquire.cta.shared::cta.b64 P1, [%0], %1, 0x989680;\n\t" \
            "@P1 bra.uni WAIT_DONE_%=;\n\t" \
            "bra.uni WAIT_LOOP_%=;\n\t" \
            "WAIT_DONE_%=:\n\t}" \
            :: "r"(_mbar), "r"(_parity) : "memory"); \
    } \
} while(0)

__device__ __forceinline__ void ldsm_x4(uint32_t& r0, uint32_t& r1, uint32_t& r2, uint32_t& r3,
                                        uint32_t addr) {
    asm volatile("ldmatrix.sync.aligned.m8n8.x4.shared.b16 {%0,%1,%2,%3}, [%4];"
                 : "=r"(r0), "=r"(r1), "=r"(r2), "=r"(r3) : "r"(addr));
}
// m16n8k16 fp16 MMA, fp32 accumulate
__device__ __forceinline__ void mma_f16(float& c0, float& c1, float& c2, float& c3,
                                        uint32_t a0, uint32_t a1, uint32_t a2, uint32_t a3,
                                        uint32_t b0, uint32_t b1) {
    asm volatile(
        "mma.sync.aligned.m16n8k16.row.col.f32.f16.f16.f32 "
        "{%0,%1,%2,%3}, {%4,%5,%6,%7}, {%8,%9}, {%0,%1,%2,%3};"
        : "+f"(c0), "+f"(c1), "+f"(c2), "+f"(c3)
        : "r"(a0), "r"(a1), "r"(a2), "r"(a3), "r"(b0), "r"(b1));
}

// ---------------- kernel 1: merged preprocessing (proven) ----------------
static constexpr int N_SOFTMAX_BLOCKS = BB * TC / 8;                    // 2048
static constexpr int N_TRANSPOSE_BLOCKS = (DD / 32) * (TQ / 32) * BB;   // 8192

__global__ __launch_bounds__(256) void pre_kernel(const float* __restrict__ sim,
                                                  const float* __restrict__ q) {
    const int bid = blockIdx.x;
    const int tid = threadIdx.x;

    if (bid < N_SOFTMAX_BLOCKS) {
        const int warp = tid >> 5;
        const int lane = tid & 31;
        const size_t row = (size_t)bid * 8 + warp;

        const float4* in = reinterpret_cast<const float4*>(sim + row * TQ);
        float4 v[8];
        #pragma unroll
        for (int j = 0; j < 8; j++) v[j] = in[lane + 32 * j];

        float m = -1e30f;
        #pragma unroll
        for (int j = 0; j < 8; j++)
            m = fmaxf(m, fmaxf(fmaxf(v[j].x, v[j].y), fmaxf(v[j].z, v[j].w)));
        #pragma unroll
        for (int o = 16; o > 0; o >>= 1) m = fmaxf(m, __shfl_xor_sync(0xFFFFFFFFu, m, o));

        float sum = 0.f;
        #pragma unroll
        for (int j = 0; j < 8; j++) {
            v[j].x = __expf(v[j].x - m); v[j].y = __expf(v[j].y - m);
            v[j].z = __expf(v[j].z - m); v[j].w = __expf(v[j].w - m);
            sum += (v[j].x + v[j].y) + (v[j].z + v[j].w);
        }
        #pragma unroll
        for (int o = 16; o > 0; o >>= 1) sum += __shfl_xor_sync(0xFFFFFFFFu, sum, o);
        const float inv = 1.0f / sum;

        uint2* orow = reinterpret_cast<uint2*>(g_attn + row * TQ);
        #pragma unroll
        for (int j = 0; j < 8; j++) {
            __half2 h01 = __floats2half2_rn(v[j].x * inv, v[j].y * inv);
            __half2 h23 = __floats2half2_rn(v[j].z * inv, v[j].w * inv);
            uint2 pk;
            pk.x = *reinterpret_cast<uint32_t*>(&h01);
            pk.y = *reinterpret_cast<uint32_t*>(&h23);
            orow[lane + 32 * j] = pk;
        }
    } else {
        __shared__ float tile[32][33];
        const int t = bid - N_SOFTMAX_BLOCKS;
        const int dt = t & 31;
        const int qt = (t >> 5) & 31;
        const int b = t >> 10;
        const int tx = tid & 31;
        const int ty = tid >> 5;
        const float* src = q + (size_t)b * TQ * DD;
        #pragma unroll
        for (int i = 0; i < 4; i++) {
            int qq = qt * 32 + ty + i * 8;
            tile[ty + i * 8][tx] = src[(size_t)qq * DD + dt * 32 + tx];
        }
        __syncthreads();
        __half* dst = g_qt + (size_t)b * DD * TQ;
        #pragma unroll
        for (int i = 0; i < 4; i++) {
            int d2 = dt * 32 + ty + i * 8;
            dst[(size_t)d2 * TQ + qt * 32 + tx] = __float2half_rn(tile[tx][ty + i * 8]);
        }
    }
}

// ---------------- kernel 2: persistent FP16 GEMM (R13 geometry) + bulk-copy producer ----------------
// CTA 128x128, 8 warps (2 M x 4 N), warp tile 64x32, KC=64, 3-stage ring, 2 CTAs/SM.
// Loads via cp.async.bulk (128 B/row, warp 0 only) -> 256 ops/chunk vs 2048 LDGSTS.
static constexpr int KC = 64;
static constexpr int NCH = TQ / KC;              // 16 k-chunks per tile
static constexpr int SROW = 72;                  // smem row stride (halves): ldmatrix conflict-free
static constexpr int A_BYTES = 128 * SROW * 2;   // 18432
static constexpr int STAGE_BYTES = 2 * A_BYTES;  // 36864
static constexpr int STAGES = 3;
static constexpr int MBAR_BYTES = 64;            // 3 mbarriers at smem base (+padding)
static constexpr int SMEM_BYTES = MBAR_BYTES + STAGES * STAGE_BYTES;  // 110656 (x2 = 221312)
static constexpr uint32_t STAGE_TX = 256 * 128;  // bytes per stage: 256 rows x 128B = 32768
static constexpr int TOTAL_TILES = (DD / 128) * (TC / 128) * BB;  // 1024
static constexpr int NCTA = 304;                 // 2 CTAs/SM x 152 SMs

__global__ __launch_bounds__(256, 2) void gemm_f16_kernel(float* __restrict__ out) {
    extern __shared__ __half smem[];
    const int tid = threadIdx.x;
    const int wid = tid >> 5, lane = tid & 31;
    const int qg = lane >> 2, t = lane & 3;         // mma groupID / threadID-in-group
    const int wm = (wid & 1) * 64;
    const int wn = (wid >> 1) * 32;
    const int cta = blockIdx.x;

    const int ntiles = (TOTAL_TILES - cta + NCTA - 1) / NCTA;
    const int total = ntiles * NCH;

    const uint32_t mbar_base = smem_u32(smem);              // 3 x 8B mbarriers
    const uint32_t tile_base = mbar_base + MBAR_BYTES;      // stage data

    if (tid == 0) {
        MBARRIER_INIT(mbar_base + 0, 1);
        MBARRIER_INIT(mbar_base + 8, 1);
        MBARRIER_INIT(mbar_base + 16, 1);
    }
    __syncthreads();

    // producer: warp 0 issues 8 bulk row-copies per chunk (4 A rows + 4 B rows per lane... 8 rows total)
    auto fetch = [&](int gc) {
        const int tl = cta + (gc >> 4) * NCTA;
        const int kc = gc & 15;
        const int dt = tl & 7, ct = (tl >> 3) & 15, bb = tl >> 7;
        const int stg = gc % 3;
        const uint32_t mb = mbar_base + stg * 8;
        if (lane == 0) MBARRIER_EXPECT_TX(mb, STAGE_TX);
        __syncwarp();
        uint32_t sa = tile_base + (uint32_t)(stg * STAGE_BYTES);
        uint32_t sb = sa + (uint32_t)A_BYTES;
        const __half* Ag = g_attn + ((size_t)bb * TC + (size_t)ct * 128) * TQ + kc * KC;
        const __half* Bg = g_qt + ((size_t)bb * DD + (size_t)dt * 128) * TQ + kc * KC;
        #pragma unroll
        for (int i = 0; i < 4; i++) {
            int row = lane + i * 32;
            bulk_g2s(sa + (uint32_t)(row * SROW * 2), Ag + (size_t)row * TQ, 128u, mb);
            bulk_g2s(sb + (uint32_t)(row * SROW * 2), Bg + (size_t)row * TQ, 128u, mb);
        }
    };

    // ldmatrix per-lane addressing (precomputed)
    const int a_row = wm + (lane & 15);                   // + i*16
    const int a_col = (lane >> 4) * 8;                    // + k0
    const int b_row = wn + (lane & 7) + (lane >> 4) * 8;  // + j2*16
    const int b_col = ((lane >> 3) & 1) * 8;              // + k0

    float acc[4][4][4];
    #pragma unroll
    for (int i = 0; i < 4; i++)
        #pragma unroll
        for (int j = 0; j < 4; j++)
            #pragma unroll
            for (int r = 0; r < 4; r++) acc[i][j][r] = 0.f;

    if (wid == 0) { fetch(0); fetch(1); }

    int tile = cta;
    for (int gc = 0; gc < total; gc++) {
        // wait for this chunk's data (parity flips each ring wrap)
        MBARRIER_WAIT_PARITY(mbar_base + (gc % 3) * 8, (gc / 3) & 1);
        __syncthreads();   // all warps done reading stage (gc-1): safe to refetch it

        if (wid == 0 && gc + 2 < total) fetch(gc + 2);

        const int stg = gc % 3;
        const uint32_t sA = tile_base + (uint32_t)(stg * STAGE_BYTES);
        const uint32_t sB = sA + (uint32_t)A_BYTES;

        #pragma unroll
        for (int ks = 0; ks < 4; ks++) {
            const int k0 = ks * 16;
            uint32_t af[4][4], bf[4][2];
            #pragma unroll
            for (int i = 0; i < 4; i++)
                ldsm_x4(af[i][0], af[i][1], af[i][2], af[i][3],
                        sA + (uint32_t)((a_row + i * 16) * SROW + k0 + a_col) * 2u);
            #pragma unroll
            for (int j2 = 0; j2 < 2; j2++)
                ldsm_x4(bf[j2 * 2][0], bf[j2 * 2][1], bf[j2 * 2 + 1][0], bf[j2 * 2 + 1][1],
                        sB + (uint32_t)((b_row + j2 * 16) * SROW + k0 + b_col) * 2u);
            #pragma unroll
            for (int i = 0; i < 4; i++)
                #pragma unroll
                for (int j = 0; j < 4; j++)
                    mma_f16(acc[i][j][0], acc[i][j][1], acc[i][j][2], acc[i][j][3],
                            af[i][0], af[i][1], af[i][2], af[i][3],
                            bf[j][0], bf[j][1]);
        }

        // tile boundary: store epilogue from registers (next tile's chunks already in flight)
        if ((gc & 15) == 15) {
            const int dt = tile & 7, ct = (tile >> 3) & 15, bb = tile >> 7;
            const size_t orow0 = (size_t)bb * TC + ct * 128 + wm + qg;
            const int col0 = dt * 128 + wn + t * 2;
            #pragma unroll
            for (int i = 0; i < 4; i++) {
                float* p0 = out + (orow0 + i * 16) * DD + col0;
                float* p1 = p0 + 8 * DD;
                #pragma unroll
                for (int j = 0; j < 4; j++) {
                    *reinterpret_cast<float2*>(p0 + j * 8) = make_float2(acc[i][j][0], acc[i][j][1]);
                    *reinterpret_cast<float2*>(p1 + j * 8) = make_float2(acc[i][j][2], acc[i][j][3]);
                    acc[i][j][0] = 0.f; acc[i][j][1] = 0.f;
                    acc[i][j][2] = 0.f; acc[i][j][3] = 0.f;
                }
            }
            tile += NCTA;
        }
    }
}

// ---------------- launcher ----------------
extern "C" void kernel_launch(void* const* d_in, const int* in_sizes, int n_in,
                              void* d_out, int out_size) {
    const float* sim  = (const float*)d_in[0];   // [8, 2048, 1024] fp32
    const float* qenc = (const float*)d_in[1];   // [8, 1024, 1024] fp32
    float* out = (float*)d_out;                  // [8, 2048, 1024] fp32

    cudaFuncSetAttribute(gemm_f16_kernel, cudaFuncAttributeMaxDynamicSharedMemorySize, SMEM_BYTES);

    pre_kernel<<<N_SOFTMAX_BLOCKS + N_TRANSPOSE_BLOCKS, 256>>>(sim, qenc);
    gemm_f16_kernel<<<NCTA, 256, SMEM_BYTES>>>(out);
}

// round 17
// speedup vs baseline: 3.8298x; 3.8298x over previous
#include <cuda_runtime.h>
#include <cuda_fp16.h>
#include <cstdint>
#include <cstddef>

// Problem dims (fixed by the dataset)
#define BB 8
#define TC 2048
#define TQ 1024
#define DD 1024

// ---------------- scratch (allocation-free: __device__ globals) ----------------
__device__ __align__(256) __half g_attn[(size_t)BB * TC * TQ];  // fp16 softmax probs, 32 MiB
__device__ __align__(256) __half g_qt[(size_t)BB * DD * TQ];    // fp16 qencode^T [b][d][q], 16 MiB
__device__ int g_tile_counter;                                   // dynamic tile queue head

// ---------------- helpers ----------------
__device__ __forceinline__ uint32_t smem_u32(const void* p) {
    uint32_t a;
    asm("{ .reg .u64 t; cvta.to.shared.u64 t, %1; cvt.u32.u64 %0, t; }" : "=r"(a) : "l"(p));
    return a;
}
__device__ __forceinline__ void cp_async16(uint32_t s, const void* g) {
    asm volatile("cp.async.cg.shared.global [%0], [%1], 16;" :: "r"(s), "l"(g) : "memory");
}
__device__ __forceinline__ void cp_commit() {
    asm volatile("cp.async.commit_group;" ::: "memory");
}
template <int N>
__device__ __forceinline__ void cp_wait() {
    asm volatile("cp.async.wait_group %0;" :: "n"(N) : "memory");
}
__device__ __forceinline__ void ldsm_x4(uint32_t& r0, uint32_t& r1, uint32_t& r2, uint32_t& r3,
                                        uint32_t addr) {
    asm volatile("ldmatrix.sync.aligned.m8n8.x4.shared.b16 {%0,%1,%2,%3}, [%4];"
                 : "=r"(r0), "=r"(r1), "=r"(r2), "=r"(r3) : "r"(addr));
}
// m16n8k16 fp16 MMA, fp32 accumulate
__device__ __forceinline__ void mma_f16(float& c0, float& c1, float& c2, float& c3,
                                        uint32_t a0, uint32_t a1, uint32_t a2, uint32_t a3,
                                        uint32_t b0, uint32_t b1) {
    asm volatile(
        "mma.sync.aligned.m16n8k16.row.col.f32.f16.f16.f32 "
        "{%0,%1,%2,%3}, {%4,%5,%6,%7}, {%8,%9}, {%0,%1,%2,%3};"
        : "+f"(c0), "+f"(c1), "+f"(c2), "+f"(c3)
        : "r"(a0), "r"(a1), "r"(a2), "r"(a3), "r"(b0), "r"(b1));
}

// ---------------- kernel 1: merged preprocessing (proven) + queue reset ----------------
static constexpr int N_SOFTMAX_BLOCKS = BB * TC / 8;                    // 2048
static constexpr int N_TRANSPOSE_BLOCKS = (DD / 32) * (TQ / 32) * BB;   // 8192
static constexpr int NCTA = 304;                 // 2 CTAs/SM x 152 SMs

__global__ __launch_bounds__(256) void pre_kernel(const float* __restrict__ sim,
                                                  const float* __restrict__ q) {
    const int bid = blockIdx.x;
    const int tid = threadIdx.x;

    if (bid == 0 && tid == 0) g_tile_counter = NCTA;   // reset dynamic queue each launch/replay

    if (bid < N_SOFTMAX_BLOCKS) {
        const int warp = tid >> 5;
        const int lane = tid & 31;
        const size_t row = (size_t)bid * 8 + warp;

        const float4* in = reinterpret_cast<const float4*>(sim + row * TQ);
        float4 v[8];
        #pragma unroll
        for (int j = 0; j < 8; j++) v[j] = in[lane + 32 * j];

        float m = -1e30f;
        #pragma unroll
        for (int j = 0; j < 8; j++)
            m = fmaxf(m, fmaxf(fmaxf(v[j].x, v[j].y), fmaxf(v[j].z, v[j].w)));
        #pragma unroll
        for (int o = 16; o > 0; o >>= 1) m = fmaxf(m, __shfl_xor_sync(0xFFFFFFFFu, m, o));

        float sum = 0.f;
        #pragma unroll
        for (int j = 0; j < 8; j++) {
            v[j].x = __expf(v[j].x - m); v[j].y = __expf(v[j].y - m);
            v[j].z = __expf(v[j].z - m); v[j].w = __expf(v[j].w - m);
            sum += (v[j].x + v[j].y) + (v[j].z + v[j].w);
        }
        #pragma unroll
        for (int o = 16; o > 0; o >>= 1) sum += __shfl_xor_sync(0xFFFFFFFFu, sum, o);
        const float inv = 1.0f / sum;

        uint2* orow = reinterpret_cast<uint2*>(g_attn + row * TQ);
        #pragma unroll
        for (int j = 0; j < 8; j++) {
            __half2 h01 = __floats2half2_rn(v[j].x * inv, v[j].y * inv);
            __half2 h23 = __floats2half2_rn(v[j].z * inv, v[j].w * inv);
            uint2 pk;
            pk.x = *reinterpret_cast<uint32_t*>(&h01);
            pk.y = *reinterpret_cast<uint32_t*>(&h23);
            orow[lane + 32 * j] = pk;
        }
    } else {
        __shared__ float tile[32][33];
        const int t = bid - N_SOFTMAX_BLOCKS;
        const int dt = t & 31;
        const int qt = (t >> 5) & 31;
        const int b = t >> 10;
        const int tx = tid & 31;
        const int ty = tid >> 5;
        const float* src = q + (size_t)b * TQ * DD;
        #pragma unroll
        for (int i = 0; i < 4; i++) {
            int qq = qt * 32 + ty + i * 8;
            tile[ty + i * 8][tx] = src[(size_t)qq * DD + dt * 32 + tx];
        }
        __syncthreads();
        __half* dst = g_qt + (size_t)b * DD * TQ;
        #pragma unroll
        for (int i = 0; i < 4; i++) {
            int d2 = dt * 32 + ty + i * 8;
            dst[(size_t)d2 * TQ + qt * 32 + tx] = __float2half_rn(tile[tx][ty + i * 8]);
        }
    }
}

// ---------------- kernel 2: persistent FP16 GEMM, dynamic tile queue ----------------
// R13 geometry: CTA 128x128, 8 warps (2Mx4N), warp tile 64x32, KC=64, 3-stage LDGSTS ring,
// 2 CTAs/SM. Tiles pulled from a global atomic counter (hardware-like work stealing);
// next tile grabbed at chunk 13 so the flat pipeline prefetches across tile boundaries.
static constexpr int KC = 64;
static constexpr int NCH = TQ / KC;              // 16 k-chunks per tile
static constexpr int SROW = 72;                  // smem row stride (halves): ldmatrix conflict-free
static constexpr int A_BYTES = 128 * SROW * 2;   // 18432
static constexpr int STAGE_BYTES = 2 * A_BYTES;  // 36864
static constexpr int STAGES = 3;
static constexpr int SMEM_BYTES = STAGES * STAGE_BYTES;  // 110592 (x2 CTAs = 221184)
static constexpr int TOTAL_TILES = (DD / 128) * (TC / 128) * BB;  // 1024

__global__ __launch_bounds__(256, 2) void gemm_f16_kernel(float* __restrict__ out) {
    extern __shared__ __half smem[];
    __shared__ int s_next;
    const int tid = threadIdx.x;
    const int wid = tid >> 5, lane = tid & 31;
    const int qg = lane >> 2, t = lane & 3;         // mma groupID / threadID-in-group
    const int wm = (wid & 1) * 64;
    const int wn = (wid >> 1) * 32;

    const uint32_t smem_base = smem_u32(smem);

    const int f_row0 = tid >> 3;            // +32 per i
    const int f_ch = tid & 7;               // 16B chunk within row

    // fetch chunk kc of tile tl into ring stage stg
    auto fetch = [&](int tl, int kc, int stg) {
        const int dt = tl & 7, ct = (tl >> 3) & 15, bb = tl >> 7;
        const __half* Ag = g_attn + ((size_t)bb * TC + (size_t)ct * 128) * TQ + kc * KC + f_ch * 8;
        const __half* Bg = g_qt + ((size_t)bb * DD + (size_t)dt * 128) * TQ + kc * KC + f_ch * 8;
        uint32_t sa = smem_base + (uint32_t)(stg * STAGE_BYTES);
        uint32_t sb = sa + (uint32_t)A_BYTES;
        #pragma unroll
        for (int i = 0; i < 4; i++) {
            int row = f_row0 + i * 32;
            uint32_t so = (uint32_t)(row * SROW + f_ch * 8) * 2u;
            cp_async16(sa + so, Ag + (size_t)row * TQ);
            cp_async16(sb + so, Bg + (size_t)row * TQ);
        }
    };

    // ldmatrix per-lane addressing (precomputed)
    const int a_row = wm + (lane & 15);                   // + i*16
    const int a_col = (lane >> 4) * 8;                    // + k0
    const int b_row = wn + (lane & 7) + (lane >> 4) * 8;  // + j2*16
    const int b_col = ((lane >> 3) & 1) * 8;              // + k0

    float acc[4][4][4];
    #pragma unroll
    for (int i = 0; i < 4; i++)
        #pragma unroll
        for (int j = 0; j < 4; j++)
            #pragma unroll
            for (int r = 0; r < 4; r++) acc[i][j][r] = 0.f;

    int tile = blockIdx.x;
    int gc = 0;
    fetch(tile, 0, 0); cp_commit();
    fetch(tile, 1, 1); cp_commit();

    while (true) {
        #pragma unroll 1
        for (int kc = 0; kc < NCH; kc++, gc++) {
            cp_wait<STAGES - 2>();
            __syncthreads();

            if (kc == 13 && tid == 0) s_next = atomicAdd(&g_tile_counter, 1);

            if (kc + 2 < NCH) {
                fetch(tile, kc + 2, (gc + 2) % 3);
            } else {
                int nt = s_next;                    // published by the syncthreads above
                if (nt < TOTAL_TILES) fetch(nt, kc + 2 - NCH, (gc + 2) % 3);
            }
            cp_commit();

            const uint32_t sA = smem_base + (uint32_t)((gc % 3) * STAGE_BYTES);
            const uint32_t sB = sA + (uint32_t)A_BYTES;

            #pragma unroll
            for (int ks = 0; ks < 4; ks++) {
                const int k0 = ks * 16;
                uint32_t af[4][4], bf[4][2];
                #pragma unroll
                for (int i = 0; i < 4; i++)
                    ldsm_x4(af[i][0], af[i][1], af[i][2], af[i][3],
                            sA + (uint32_t)((a_row + i * 16) * SROW + k0 + a_col) * 2u);
                #pragma unroll
                for (int j2 = 0; j2 < 2; j2++)
                    ldsm_x4(bf[j2 * 2][0], bf[j2 * 2][1], bf[j2 * 2 + 1][0], bf[j2 * 2 + 1][1],
                            sB + (uint32_t)((b_row + j2 * 16) * SROW + k0 + b_col) * 2u);
                #pragma unroll
                for (int i = 0; i < 4; i++)
                    #pragma unroll
                    for (int j = 0; j < 4; j++)
                        mma_f16(acc[i][j][0], acc[i][j][1], acc[i][j][2], acc[i][j][3],
                                af[i][0], af[i][1], af[i][2], af[i][3],
                                bf[j][0], bf[j][1]);
            }
        }

        // epilogue: store this tile from registers (next tile's chunks already in flight)
        {
            const int dt = tile & 7, ct = (tile >> 3) & 15, bb = tile >> 7;
            const size_t orow0 = (size_t)bb * TC + ct * 128 + wm + qg;
            const int col0 = dt * 128 + wn + t * 2;
            #pragma unroll
            for (int i = 0; i < 4; i++) {
                float* p0 = out + (orow0 + i * 16) * DD + col0;
                float* p1 = p0 + 8 * DD;
                #pragma unroll
                for (int j = 0; j < 4; j++) {
                    *reinterpret_cast<float2*>(p0 + j * 8) = make_float2(acc[i][j][0], acc[i][j][1]);
                    *reinterpret_cast<float2*>(p1 + j * 8) = make_float2(acc[i][j][2], acc[i][j][3]);
                    acc[i][j][0] = 0.f; acc[i][j][1] = 0.f;
                    acc[i][j][2] = 0.f; acc[i][j][3] = 0.f;
                }
            }
        }

        tile = s_next;                              // safe: last write was kc==13, synced since
        if (tile >= TOTAL_TILES) break;
    }
}

// ---------------- launcher ----------------
extern "C" void kernel_launch(void* const* d_in, const int* in_sizes, int n_in,
                              void* d_out, int out_size) {
    const float* sim  = (const float*)d_in[0];   // [8, 2048, 1024] fp32
    const float* qenc = (const float*)d_in[1];   // [8, 1024, 1024] fp32
    float* out = (float*)d_out;                  // [8, 2048, 1024] fp32

    cudaFuncSetAttribute(gemm_f16_kernel, cudaFuncAttributeMaxDynamicSharedMemorySize, SMEM_BYTES);

    pre_kernel<<<N_SOFTMAX_BLOCKS + N_TRANSPOSE_BLOCKS, 256>>>(sim, qenc);
    gemm_f16_kernel<<<NCTA, 256, SMEM_BYTES>>>(out);
}